// round 9
// baseline (speedup 1.0000x reference)
#include <cuda_runtime.h>
#include <cuda_fp16.h>
#include <math.h>

#define D 128
#define SLOPE 0.2f
#define BN_EPS 1e-5f
#define MAXN 50048
#define MAXET 901120

// GEMM tile config: 256-row M tile, full K=128 resident in smem
#define GM_MT 256
#define GM_AS_STRIDE 132
#define GM_SMEM_BYTES ((GM_MT * GM_AS_STRIDE + 128 * GM_AS_STRIDE) * 4)

// GAT kernel launch shape: pooled strided warp scheduling
#define GAT_BLOCKS 592
#define GAT_THREADS 256
#define GAT_WARPS (GAT_BLOCKS * (GAT_THREADS / 32))

// ---------------- scratch (static device globals: allocation-free) ----------------
__device__ __align__(16) __half g_xl_h[MAXN * D];   // fp16 source-transform (gathered)
__device__ __align__(16) float g_xr[MAXN * D];
__device__ __align__(16) float g_xres[MAXN * D];
__device__ __align__(16) float g_h[MAXN * D];
__device__ int g_deg[MAXN];
__device__ int g_cursor[MAXN];
__device__ int g_rowptr[MAXN + 1];
__device__ int g_col[MAXET];
__device__ int g_bsum[64];
__device__ double g_dsum[D];
__device__ double g_dsq[D];
__device__ __align__(16) float g_scale[D];
__device__ __align__(16) float g_shift[D];
__device__ int g_ticket;

// int64-vs-int32 probe: odd 32-bit words of the first 8 values all zero => int64.
__device__ __forceinline__ int probe_is64(const unsigned int* __restrict__ p) {
    unsigned int o = 0;
#pragma unroll
    for (int j = 1; j < 16; j += 2) o |= p[j];
    return o == 0u;
}

// ---------------- CSR build ----------------
__global__ void k_count(const void* __restrict__ ei, int E, int N) {
    __shared__ int s64;
    if (threadIdx.x == 0) s64 = probe_is64((const unsigned int*)ei);
    __syncthreads();
    int is64 = s64;
    int t = blockIdx.x * blockDim.x + threadIdx.x;
    int Et = E + N;
    if (t >= Et) return;
    int d;
    if (t < E) {
        d = is64 ? (int)((const long long*)ei)[(long long)E + t]
                 : ((const int*)ei)[E + t];
    } else {
        d = t - E;  // self loop
    }
    atomicAdd(&g_deg[d], 1);
}

__global__ void k_scan1(int N) {
    __shared__ int s[1024];
    int tid = threadIdx.x;
    int i = blockIdx.x * 1024 + tid;
    int v = (i < N) ? g_deg[i] : 0;
    if (i < N) { g_deg[i] = 0; g_cursor[i] = 0; }  // restore zeros for next call
    s[tid] = v;
    __syncthreads();
    for (int off = 1; off < 1024; off <<= 1) {
        int t = 0;
        if (tid >= off) t = s[tid - off];
        __syncthreads();
        if (tid >= off) s[tid] += t;
        __syncthreads();
    }
    if (i < N) g_rowptr[i + 1] = s[tid];
    if (tid == 1023) g_bsum[blockIdx.x] = s[1023];
}

__global__ void k_scan3(int N) {
    __shared__ int sbase;
    if (threadIdx.x == 0) {
        int acc = 0;
        for (int b = 0; b < blockIdx.x; b++) acc += g_bsum[b];
        sbase = acc;
    }
    __syncthreads();
    int i = blockIdx.x * 1024 + threadIdx.x;
    if (i < N) g_rowptr[i + 1] += sbase;
    if (i == 0) g_rowptr[0] = 0;
}

__global__ void k_scatter(const void* __restrict__ ei, int E, int N) {
    __shared__ int s64;
    if (threadIdx.x == 0) s64 = probe_is64((const unsigned int*)ei);
    __syncthreads();
    int is64 = s64;
    int t = blockIdx.x * blockDim.x + threadIdx.x;
    int Et = E + N;
    if (t >= Et) return;
    int s, d;
    if (t < E) {
        if (is64) {
            s = (int)((const long long*)ei)[t];
            d = (int)((const long long*)ei)[(long long)E + t];
        } else {
            s = ((const int*)ei)[t];
            d = ((const int*)ei)[E + t];
        }
    } else {
        s = d = t - E;
    }
    int pos = g_rowptr[d] + atomicAdd(&g_cursor[d], 1);
    g_col[pos] = s;
}

// ---------------- tf32 tensor-core GEMM (whole-K, single sync) ----------------
__device__ __forceinline__ unsigned f2tf(float x) {
    unsigned r;
    asm("cvt.rna.tf32.f32 %0, %1;" : "=r"(r) : "f"(x));
    return r;
}

__global__ void __launch_bounds__(512, 1)
k_gemm3(const float* __restrict__ A,
        const float* __restrict__ W0, const float* __restrict__ W1,
        const float* __restrict__ W2,
        void* __restrict__ C0v, float* __restrict__ C1, float* __restrict__ C2,
        const float* __restrict__ bvec, int M, int affine, int c0half) {
    const float* W = (blockIdx.y == 0) ? W0 : (blockIdx.y == 1 ? W1 : W2);
    float* C = (blockIdx.y == 0) ? (float*)C0v : (blockIdx.y == 1 ? C1 : C2);
    int ishalf = (blockIdx.y == 0) ? c0half : 0;

    extern __shared__ unsigned smem_u[];
    unsigned* As = smem_u;                            // [256][132]
    unsigned* Ws = smem_u + GM_MT * GM_AS_STRIDE;     // [128][132]

    int tid = threadIdx.x;
    int warp = tid >> 5;
    int lane = tid & 31;

    // zero BN accumulators for the following fused GAT+BN kernel
    if (blockIdx.x == 0 && blockIdx.y == 0) {
        if (tid < 128) { g_dsum[tid] = 0.0; g_dsq[tid] = 0.0; }
        if (tid == 0) g_ticket = 0;
    }

    int wm = warp >> 1;           // 0..7  -> 32-row slab
    int wn = warp & 1;            // 0..1  -> 64-col slab
    int m0 = blockIdx.x * GM_MT;

    int qr = lane >> 2;           // 0..7
    int qc = lane & 3;            // 0..3

    // ---- load full A tile (256 x 128) ----
#pragma unroll
    for (int it = 0; it < 16; it++) {
        int i = it * 512 + tid;
        int row = i >> 5;
        int col = (i & 31) * 4;
        int gm = m0 + row;
        float4 v = make_float4(0.f, 0.f, 0.f, 0.f);
        if (gm < M) v = *(const float4*)(A + (long long)gm * 128 + col);
        if (affine) {
            float4 sc = *(const float4*)(g_scale + col);
            float4 sh = *(const float4*)(g_shift + col);
            v.x = fmaf(v.x, sc.x, sh.x); v.x = v.x > 0.f ? v.x : v.x * SLOPE;
            v.y = fmaf(v.y, sc.y, sh.y); v.y = v.y > 0.f ? v.y : v.y * SLOPE;
            v.z = fmaf(v.z, sc.z, sh.z); v.z = v.z > 0.f ? v.z : v.z * SLOPE;
            v.w = fmaf(v.w, sc.w, sh.w); v.w = v.w > 0.f ? v.w : v.w * SLOPE;
        }
        unsigned* dst = As + row * GM_AS_STRIDE + col;
        dst[0] = f2tf(v.x); dst[1] = f2tf(v.y); dst[2] = f2tf(v.z); dst[3] = f2tf(v.w);
    }
    // ---- load full W (128 x 128) ----
#pragma unroll
    for (int it = 0; it < 8; it++) {
        int i = it * 512 + tid;
        int row = i >> 5;
        int col = (i & 31) * 4;
        float4 w = *(const float4*)(W + row * 128 + col);
        unsigned* dst = Ws + row * GM_AS_STRIDE + col;
        dst[0] = f2tf(w.x); dst[1] = f2tf(w.y); dst[2] = f2tf(w.z); dst[3] = f2tf(w.w);
    }
    __syncthreads();

    float acc[2][8][4];
#pragma unroll
    for (int i = 0; i < 2; i++)
#pragma unroll
        for (int j = 0; j < 8; j++)
#pragma unroll
            for (int k = 0; k < 4; k++) acc[i][j][k] = 0.f;

#pragma unroll
    for (int ks = 0; ks < 16; ks++) {
        int kb = ks * 8;
        unsigned a[2][4];
#pragma unroll
        for (int mi = 0; mi < 2; mi++) {
            int rb = wm * 32 + mi * 16 + qr;
            const unsigned* ap = As + rb * GM_AS_STRIDE + kb + qc;
            a[mi][0] = ap[0];
            a[mi][1] = ap[8 * GM_AS_STRIDE];
            a[mi][2] = ap[4];
            a[mi][3] = ap[8 * GM_AS_STRIDE + 4];
        }
#pragma unroll
        for (int ni = 0; ni < 8; ni++) {
            int n = wn * 64 + ni * 8 + qr;
            unsigned b0 = Ws[(kb + qc) * GM_AS_STRIDE + n];
            unsigned b1 = Ws[(kb + qc + 4) * GM_AS_STRIDE + n];
#pragma unroll
            for (int mi = 0; mi < 2; mi++) {
                asm volatile(
                    "mma.sync.aligned.m16n8k8.row.col.f32.tf32.tf32.f32 "
                    "{%0,%1,%2,%3}, {%4,%5,%6,%7}, {%8,%9}, {%0,%1,%2,%3};\n"
                    : "+f"(acc[mi][ni][0]), "+f"(acc[mi][ni][1]),
                      "+f"(acc[mi][ni][2]), "+f"(acc[mi][ni][3])
                    : "r"(a[mi][0]), "r"(a[mi][1]), "r"(a[mi][2]), "r"(a[mi][3]),
                      "r"(b0), "r"(b1));
            }
        }
    }

    // epilogue
    __half* Ch = (__half*)C0v;
#pragma unroll
    for (int mi = 0; mi < 2; mi++) {
        int r0 = m0 + wm * 32 + mi * 16 + qr;
#pragma unroll
        for (int ni = 0; ni < 8; ni++) {
            int col = wn * 64 + ni * 8 + qc * 2;
            float bx = 0.f, by = 0.f;
            if (bvec) { bx = bvec[col]; by = bvec[col + 1]; }
            if (ishalf) {
                if (r0 < M) {
                    __half2 o = __floats2half2_rn(acc[mi][ni][0] + bx, acc[mi][ni][1] + by);
                    *(__half2*)(Ch + (long long)r0 * 128 + col) = o;
                }
                if (r0 + 8 < M) {
                    __half2 o = __floats2half2_rn(acc[mi][ni][2] + bx, acc[mi][ni][3] + by);
                    *(__half2*)(Ch + (long long)(r0 + 8) * 128 + col) = o;
                }
            } else {
                if (r0 < M) {
                    float2 o; o.x = acc[mi][ni][0] + bx; o.y = acc[mi][ni][1] + by;
                    *(float2*)(C + (long long)r0 * 128 + col) = o;
                }
                if (r0 + 8 < M) {
                    float2 o; o.x = acc[mi][ni][2] + bx; o.y = acc[mi][ni][3] + by;
                    *(float2*)(C + (long long)(r0 + 8) * 128 + col) = o;
                }
            }
        }
    }
}

// ---------------- fused GATv2 edge pass + BN statistics + BN finalize ----------------
// Edge-pair lane layout: lanes 0-15 process edge A, lanes 16-31 edge B of each
// pair. Each lane owns 8 fp16 channels (one LDG.128 per lane covers TWO edges).
// Head of a lane = (lane&15)>>2; score reduction = 2 shfl_xor within 4-lane
// groups; one MUFU serves both edges. Halves gather-LDG/SHFL/MUFU instruction
// counts vs the 32-lane-per-edge layout. Per-half accumulators merged once per
// node via shfl_xor(16). Softmax without running max (scores bounded; clamp 80).
__global__ void __launch_bounds__(GAT_THREADS)
k_gat_bn(const __half* __restrict__ xl, const float* __restrict__ xr,
         const float* __restrict__ xres, const float* __restrict__ att,
         const float* __restrict__ bias,
         const float* __restrict__ gamma, const float* __restrict__ beta,
         float* __restrict__ h, int N) {
    __shared__ float s_sum[128];
    __shared__ float s_sq[128];
    __shared__ int s_last;

    int tid = threadIdx.x;
    if (tid < 128) { s_sum[tid] = 0.f; s_sq[tid] = 0.f; }
    __syncthreads();

    int gwarp = blockIdx.x * (GAT_THREADS / 32) + (tid >> 5);
    int lane = tid & 31;
    int eh = lane >> 4;       // 0 = edge slot A, 1 = edge slot B
    int cl = lane & 15;       // 16-lane channel slot: channels [8cl, 8cl+8)

    // per-lane 8-channel constants
    float a8[8], b8[8];
#pragma unroll
    for (int j = 0; j < 8; j += 4) {
        float4 t = *(const float4*)(att + cl * 8 + j);
        a8[j] = t.x; a8[j + 1] = t.y; a8[j + 2] = t.z; a8[j + 3] = t.w;
        float4 u = *(const float4*)(bias + cl * 8 + j);
        b8[j] = u.x; b8[j + 1] = u.y; b8[j + 2] = u.z; b8[j + 3] = u.w;
    }

    float lsum[8] = {0.f, 0.f, 0.f, 0.f, 0.f, 0.f, 0.f, 0.f};
    float lsq[8]  = {0.f, 0.f, 0.f, 0.f, 0.f, 0.f, 0.f, 0.f};

    for (int node = gwarp; node < N; node += GAT_WARPS) {
        // xr: this node's 8 channels per lane (both halves load same values)
        float xr8[8];
#pragma unroll
        for (int j = 0; j < 8; j += 4) {
            float4 t = *(const float4*)(xr + (long long)node * D + cl * 8 + j);
            xr8[j] = t.x; xr8[j + 1] = t.y; xr8[j + 2] = t.z; xr8[j + 3] = t.w;
        }

        int beg = g_rowptr[node];
        int end = g_rowptr[node + 1];

        float s = 0.f;
        float acc[8] = {0.f, 0.f, 0.f, 0.f, 0.f, 0.f, 0.f, 0.f};

        for (int e = beg; e < end; e += 2) {
            int ee = e + eh;
            bool valid = (ee < end);
            int si = g_col[valid ? ee : (end - 1)];
            // one LDG.128 per lane: 8 fp16 channels of this half's edge
            uint4 raw = *(const uint4*)(xl + (long long)si * D + cl * 8);
            float ml[8];
            {
                float2 f0 = __half22float2(*(__half2*)&raw.x);
                float2 f1 = __half22float2(*(__half2*)&raw.y);
                float2 f2 = __half22float2(*(__half2*)&raw.z);
                float2 f3 = __half22float2(*(__half2*)&raw.w);
                ml[0] = f0.x; ml[1] = f0.y; ml[2] = f1.x; ml[3] = f1.y;
                ml[4] = f2.x; ml[5] = f2.y; ml[6] = f3.x; ml[7] = f3.y;
            }
            // score partial over this lane's 8 channels
            float pt = 0.f;
#pragma unroll
            for (int j = 0; j < 8; j++) {
                float v = ml[j] + xr8[j];
                v = v > 0.f ? v : v * SLOPE;
                pt = fmaf(v, a8[j], pt);
            }
            // reduce within 4-lane head group (stays inside each half-warp)
            pt += __shfl_xor_sync(0xffffffffu, pt, 1);
            pt += __shfl_xor_sync(0xffffffffu, pt, 2);
            float p = valid ? __expf(fminf(pt, 80.f)) : 0.f;
            s += p;
#pragma unroll
            for (int j = 0; j < 8; j++) acc[j] = fmaf(p, ml[j], acc[j]);
        }

        // merge the two edge-slot halves (lane l <-> lane l+16)
        s += __shfl_xor_sync(0xffffffffu, s, 16);
#pragma unroll
        for (int j = 0; j < 8; j++) acc[j] += __shfl_xor_sync(0xffffffffu, acc[j], 16);

        float inv = 1.f / s;  // self loop guarantees s > 0

        if (eh == 0) {  // lanes 0-15 write the node's 128 channels (8 each)
            float o[8];
#pragma unroll
            for (int j = 0; j < 8; j += 4) {
                float4 r4 = *(const float4*)(xres + (long long)node * D + cl * 8 + j);
                o[j + 0] = fmaf(acc[j + 0], inv, b8[j + 0] + r4.x);
                o[j + 1] = fmaf(acc[j + 1], inv, b8[j + 1] + r4.y);
                o[j + 2] = fmaf(acc[j + 2], inv, b8[j + 2] + r4.z);
                o[j + 3] = fmaf(acc[j + 3], inv, b8[j + 3] + r4.w);
                float4 w4 = make_float4(o[j], o[j + 1], o[j + 2], o[j + 3]);
                *(float4*)(h + (long long)node * D + cl * 8 + j) = w4;
            }
#pragma unroll
            for (int j = 0; j < 8; j++) {
                lsum[j] += o[j];
                lsq[j]  += o[j] * o[j];
            }
        }
    }

    // fold BN partials: lanes 0-15 own channels [8cl, 8cl+8) exclusively
    if (eh == 0) {
#pragma unroll
        for (int j = 0; j < 8; j++) {
            atomicAdd(&s_sum[cl * 8 + j], lsum[j]);
            atomicAdd(&s_sq[cl * 8 + j],  lsq[j]);
        }
    }
    __syncthreads();

    if (tid < 128) {
        atomicAdd(&g_dsum[tid], (double)s_sum[tid]);
        atomicAdd(&g_dsq[tid],  (double)s_sq[tid]);
    }
    __threadfence();
    __syncthreads();
    if (tid == 0) {
        int t = atomicAdd(&g_ticket, 1);
        s_last = (t == (int)gridDim.x - 1) ? 1 : 0;
    }
    __syncthreads();

    if (s_last && tid < 128) {
        double mean = __ldcg(&g_dsum[tid]) / (double)N;
        double var  = __ldcg(&g_dsq[tid]) / (double)N - mean * mean;
        float inv = rsqrtf((float)var + BN_EPS);
        float sc = gamma[tid] * inv;
        g_scale[tid] = sc;
        g_shift[tid] = beta[tid] - (float)mean * sc;
    }
}

// ---------------- launch ----------------
extern "C" void kernel_launch(void* const* d_in, const int* in_sizes, int n_in,
                              void* d_out, int out_size) {
    const float* x     = (const float*)d_in[0];
    const void*  ei    = d_in[1];
    const float* Wl    = (const float*)d_in[2];
    const float* Wr    = (const float*)d_in[3];
    const float* att   = (const float*)d_in[4];
    const float* bias  = (const float*)d_in[5];
    const float* Wres  = (const float*)d_in[6];
    const float* gamma = (const float*)d_in[7];
    const float* beta  = (const float*)d_in[8];
    const float* Wout  = (const float*)d_in[9];
    const float* bout  = (const float*)d_in[10];
    int N = in_sizes[0] / D;
    int E = in_sizes[1] / 2;
    float* out = (float*)d_out;

    __half* p_xlh;
    float *p_xr, *p_xres, *p_h;
    cudaGetSymbolAddress((void**)&p_xlh, g_xl_h);
    cudaGetSymbolAddress((void**)&p_xr, g_xr);
    cudaGetSymbolAddress((void**)&p_xres, g_xres);
    cudaGetSymbolAddress((void**)&p_h, g_h);

    static cudaStream_t s2 = []() {
        cudaStream_t s; cudaStreamCreateWithFlags(&s, cudaStreamNonBlocking); return s;
    }();
    static cudaEvent_t ev_fork = []() {
        cudaEvent_t e; cudaEventCreateWithFlags(&e, cudaEventDisableTiming); return e;
    }();
    static cudaEvent_t ev_csr = []() {
        cudaEvent_t e; cudaEventCreateWithFlags(&e, cudaEventDisableTiming); return e;
    }();
    static bool attr_ok = []() {
        cudaFuncSetAttribute(k_gemm3, cudaFuncAttributeMaxDynamicSharedMemorySize,
                             GM_SMEM_BYTES);
        return true;
    }();
    (void)attr_ok;

    int Et = E + N;
    int nb = (N + 1023) / 1024;

    int mtiles = (N + GM_MT - 1) / GM_MT;
    dim3 g3(mtiles, 3);
    dim3 g1(mtiles, 1);

    // fork: CSR build on s2, overlapped with layer-0 GEMM on the main stream
    cudaEventRecord(ev_fork, 0);
    k_gemm3<<<g3, 512, GM_SMEM_BYTES>>>(x, Wl, Wr, Wres,
                                        p_xlh, p_xr, p_xres, nullptr, N, 0, 1);
    cudaStreamWaitEvent(s2, ev_fork, 0);
    k_count<<<(Et + 255) / 256, 256, 0, s2>>>(ei, E, N);
    k_scan1<<<nb, 1024, 0, s2>>>(N);
    k_scan3<<<nb, 1024, 0, s2>>>(N);
    k_scatter<<<(Et + 255) / 256, 256, 0, s2>>>(ei, E, N);
    cudaEventRecord(ev_csr, s2);
    cudaStreamWaitEvent(0, ev_csr, 0);  // join CSR before first edge pass

    const float* xin = x;
    for (int l = 0; l < 3; l++) {
        if (l > 0) {
            k_gemm3<<<g3, 512, GM_SMEM_BYTES>>>(xin,
                                                Wl + l * D * D, Wr + l * D * D,
                                                Wres + l * D * D,
                                                p_xlh, p_xr, p_xres, nullptr, N, 1, 1);
        }
        k_gat_bn<<<GAT_BLOCKS, GAT_THREADS>>>(p_xlh, p_xr, p_xres, att + l * D,
                                              bias + l * D, gamma + l * D,
                                              beta + l * D, p_h, N);
        xin = p_h;
    }
    k_gemm3<<<g1, 512, GM_SMEM_BYTES>>>(p_h, Wout, Wout, Wout,
                                        out, out, out, bout, N, 1, 0);
}

// round 10
// speedup vs baseline: 1.0810x; 1.0810x over previous
#include <cuda_runtime.h>
#include <cuda_fp16.h>
#include <math.h>

#define D 128
#define SLOPE 0.2f
#define BN_EPS 1e-5f
#define MAXN 50048
#define MAXET 901120

// GEMM tile config: 256-row M tile, full K=128 resident in smem
#define GM_MT 256
#define GM_AS_STRIDE 132
#define GM_SMEM_BYTES ((GM_MT * GM_AS_STRIDE + 128 * GM_AS_STRIDE) * 4)

// GAT kernel launch shape: pooled strided warp scheduling
#define GAT_BLOCKS 592
#define GAT_THREADS 256
#define GAT_WARPS (GAT_BLOCKS * (GAT_THREADS / 32))

// ---------------- scratch (static device globals: allocation-free) ----------------
__device__ __align__(16) __half g_xl_h[MAXN * D];   // fp16 source-transform (gathered)
__device__ __align__(16) float g_xr[MAXN * D];
__device__ __align__(16) float g_xres[MAXN * D];
__device__ __align__(16) float g_h[MAXN * D];
__device__ int g_deg[MAXN];
__device__ int g_cursor[MAXN];
__device__ int g_rowptr[MAXN + 1];
__device__ int g_col[MAXET];
__device__ int g_bsum[64];
__device__ double g_dsum[D];
__device__ double g_dsq[D];
__device__ __align__(16) float g_scale[D];
__device__ __align__(16) float g_shift[D];
__device__ int g_ticket;

// int64-vs-int32 probe: odd 32-bit words of the first 8 values all zero => int64.
__device__ __forceinline__ int probe_is64(const unsigned int* __restrict__ p) {
    unsigned int o = 0;
#pragma unroll
    for (int j = 1; j < 16; j += 2) o |= p[j];
    return o == 0u;
}

// ---------------- CSR build ----------------
__global__ void k_count(const void* __restrict__ ei, int E, int N) {
    __shared__ int s64;
    if (threadIdx.x == 0) s64 = probe_is64((const unsigned int*)ei);
    __syncthreads();
    int is64 = s64;
    int t = blockIdx.x * blockDim.x + threadIdx.x;
    int Et = E + N;
    if (t >= Et) return;
    int d;
    if (t < E) {
        d = is64 ? (int)((const long long*)ei)[(long long)E + t]
                 : ((const int*)ei)[E + t];
    } else {
        d = t - E;  // self loop
    }
    atomicAdd(&g_deg[d], 1);
}

__global__ void k_scan1(int N) {
    __shared__ int s[1024];
    int tid = threadIdx.x;
    int i = blockIdx.x * 1024 + tid;
    int v = (i < N) ? g_deg[i] : 0;
    if (i < N) { g_deg[i] = 0; g_cursor[i] = 0; }  // restore zeros for next call
    s[tid] = v;
    __syncthreads();
    for (int off = 1; off < 1024; off <<= 1) {
        int t = 0;
        if (tid >= off) t = s[tid - off];
        __syncthreads();
        if (tid >= off) s[tid] += t;
        __syncthreads();
    }
    if (i < N) g_rowptr[i + 1] = s[tid];
    if (tid == 1023) g_bsum[blockIdx.x] = s[1023];
}

__global__ void k_scan3(int N) {
    __shared__ int sbase;
    if (threadIdx.x == 0) {
        int acc = 0;
        for (int b = 0; b < blockIdx.x; b++) acc += g_bsum[b];
        sbase = acc;
    }
    __syncthreads();
    int i = blockIdx.x * 1024 + threadIdx.x;
    if (i < N) g_rowptr[i + 1] += sbase;
    if (i == 0) g_rowptr[0] = 0;
}

__global__ void k_scatter(const void* __restrict__ ei, int E, int N) {
    __shared__ int s64;
    if (threadIdx.x == 0) s64 = probe_is64((const unsigned int*)ei);
    __syncthreads();
    int is64 = s64;
    int t = blockIdx.x * blockDim.x + threadIdx.x;
    int Et = E + N;
    if (t >= Et) return;
    int s, d;
    if (t < E) {
        if (is64) {
            s = (int)((const long long*)ei)[t];
            d = (int)((const long long*)ei)[(long long)E + t];
        } else {
            s = ((const int*)ei)[t];
            d = ((const int*)ei)[E + t];
        }
    } else {
        s = d = t - E;
    }
    int pos = g_rowptr[d] + atomicAdd(&g_cursor[d], 1);
    g_col[pos] = s;
}

// ---------------- tf32 tensor-core GEMM (whole-K, single sync) ----------------
__device__ __forceinline__ unsigned f2tf(float x) {
    unsigned r;
    asm("cvt.rna.tf32.f32 %0, %1;" : "=r"(r) : "f"(x));
    return r;
}

__global__ void __launch_bounds__(512, 1)
k_gemm3(const float* __restrict__ A,
        const float* __restrict__ W0, const float* __restrict__ W1,
        const float* __restrict__ W2,
        void* __restrict__ C0v, float* __restrict__ C1, float* __restrict__ C2,
        const float* __restrict__ bvec, int M, int affine, int c0half) {
    const float* W = (blockIdx.y == 0) ? W0 : (blockIdx.y == 1 ? W1 : W2);
    float* C = (blockIdx.y == 0) ? (float*)C0v : (blockIdx.y == 1 ? C1 : C2);
    int ishalf = (blockIdx.y == 0) ? c0half : 0;

    extern __shared__ unsigned smem_u[];
    unsigned* As = smem_u;                            // [256][132]
    unsigned* Ws = smem_u + GM_MT * GM_AS_STRIDE;     // [128][132]

    int tid = threadIdx.x;
    int warp = tid >> 5;
    int lane = tid & 31;

    // zero BN accumulators for the following fused GAT+BN kernel
    if (blockIdx.x == 0 && blockIdx.y == 0) {
        if (tid < 128) { g_dsum[tid] = 0.0; g_dsq[tid] = 0.0; }
        if (tid == 0) g_ticket = 0;
    }

    int wm = warp >> 1;           // 0..7  -> 32-row slab
    int wn = warp & 1;            // 0..1  -> 64-col slab
    int m0 = blockIdx.x * GM_MT;

    int qr = lane >> 2;           // 0..7
    int qc = lane & 3;            // 0..3

    // ---- load full A tile (256 x 128) ----
#pragma unroll
    for (int it = 0; it < 16; it++) {
        int i = it * 512 + tid;
        int row = i >> 5;
        int col = (i & 31) * 4;
        int gm = m0 + row;
        float4 v = make_float4(0.f, 0.f, 0.f, 0.f);
        if (gm < M) v = *(const float4*)(A + (long long)gm * 128 + col);
        if (affine) {
            float4 sc = *(const float4*)(g_scale + col);
            float4 sh = *(const float4*)(g_shift + col);
            v.x = fmaf(v.x, sc.x, sh.x); v.x = v.x > 0.f ? v.x : v.x * SLOPE;
            v.y = fmaf(v.y, sc.y, sh.y); v.y = v.y > 0.f ? v.y : v.y * SLOPE;
            v.z = fmaf(v.z, sc.z, sh.z); v.z = v.z > 0.f ? v.z : v.z * SLOPE;
            v.w = fmaf(v.w, sc.w, sh.w); v.w = v.w > 0.f ? v.w : v.w * SLOPE;
        }
        unsigned* dst = As + row * GM_AS_STRIDE + col;
        dst[0] = f2tf(v.x); dst[1] = f2tf(v.y); dst[2] = f2tf(v.z); dst[3] = f2tf(v.w);
    }
    // ---- load full W (128 x 128) ----
#pragma unroll
    for (int it = 0; it < 8; it++) {
        int i = it * 512 + tid;
        int row = i >> 5;
        int col = (i & 31) * 4;
        float4 w = *(const float4*)(W + row * 128 + col);
        unsigned* dst = Ws + row * GM_AS_STRIDE + col;
        dst[0] = f2tf(w.x); dst[1] = f2tf(w.y); dst[2] = f2tf(w.z); dst[3] = f2tf(w.w);
    }
    __syncthreads();

    float acc[2][8][4];
#pragma unroll
    for (int i = 0; i < 2; i++)
#pragma unroll
        for (int j = 0; j < 8; j++)
#pragma unroll
            for (int k = 0; k < 4; k++) acc[i][j][k] = 0.f;

#pragma unroll
    for (int ks = 0; ks < 16; ks++) {
        int kb = ks * 8;
        unsigned a[2][4];
#pragma unroll
        for (int mi = 0; mi < 2; mi++) {
            int rb = wm * 32 + mi * 16 + qr;
            const unsigned* ap = As + rb * GM_AS_STRIDE + kb + qc;
            a[mi][0] = ap[0];
            a[mi][1] = ap[8 * GM_AS_STRIDE];
            a[mi][2] = ap[4];
            a[mi][3] = ap[8 * GM_AS_STRIDE + 4];
        }
#pragma unroll
        for (int ni = 0; ni < 8; ni++) {
            int n = wn * 64 + ni * 8 + qr;
            unsigned b0 = Ws[(kb + qc) * GM_AS_STRIDE + n];
            unsigned b1 = Ws[(kb + qc + 4) * GM_AS_STRIDE + n];
#pragma unroll
            for (int mi = 0; mi < 2; mi++) {
                asm volatile(
                    "mma.sync.aligned.m16n8k8.row.col.f32.tf32.tf32.f32 "
                    "{%0,%1,%2,%3}, {%4,%5,%6,%7}, {%8,%9}, {%0,%1,%2,%3};\n"
                    : "+f"(acc[mi][ni][0]), "+f"(acc[mi][ni][1]),
                      "+f"(acc[mi][ni][2]), "+f"(acc[mi][ni][3])
                    : "r"(a[mi][0]), "r"(a[mi][1]), "r"(a[mi][2]), "r"(a[mi][3]),
                      "r"(b0), "r"(b1));
            }
        }
    }

    // epilogue
    __half* Ch = (__half*)C0v;
#pragma unroll
    for (int mi = 0; mi < 2; mi++) {
        int r0 = m0 + wm * 32 + mi * 16 + qr;
#pragma unroll
        for (int ni = 0; ni < 8; ni++) {
            int col = wn * 64 + ni * 8 + qc * 2;
            float bx = 0.f, by = 0.f;
            if (bvec) { bx = bvec[col]; by = bvec[col + 1]; }
            if (ishalf) {
                if (r0 < M) {
                    __half2 o = __floats2half2_rn(acc[mi][ni][0] + bx, acc[mi][ni][1] + by);
                    *(__half2*)(Ch + (long long)r0 * 128 + col) = o;
                }
                if (r0 + 8 < M) {
                    __half2 o = __floats2half2_rn(acc[mi][ni][2] + bx, acc[mi][ni][3] + by);
                    *(__half2*)(Ch + (long long)(r0 + 8) * 128 + col) = o;
                }
            } else {
                if (r0 < M) {
                    float2 o; o.x = acc[mi][ni][0] + bx; o.y = acc[mi][ni][1] + by;
                    *(float2*)(C + (long long)r0 * 128 + col) = o;
                }
                if (r0 + 8 < M) {
                    float2 o; o.x = acc[mi][ni][2] + bx; o.y = acc[mi][ni][3] + by;
                    *(float2*)(C + (long long)(r0 + 8) * 128 + col) = o;
                }
            }
        }
    }
}

// ---------------- fused GATv2 edge pass + BN statistics + BN finalize ----------------
// R7 layout (one warp per node step, lane owns 4 channels, 4-edge batches).
// Score math restructured: leaky(v) = 0.6v + 0.4|v| (exact for slope 0.2), with
// |v| as a free FFMA operand modifier and 0.6/0.4 pre-folded into the attention
// vector (a6/a4). Destination-side term sum(a6*xr) hoisted per node (t1 seed).
// Per channel: FADD + 2 FFMA (was FADD + FSETP/FSEL + FFMA).
__global__ void __launch_bounds__(GAT_THREADS)
k_gat_bn(const __half* __restrict__ xl, const float* __restrict__ xr,
         const float* __restrict__ xres, const float* __restrict__ att,
         const float* __restrict__ bias,
         const float* __restrict__ gamma, const float* __restrict__ beta,
         float* __restrict__ h, int N) {
    __shared__ float s_sum[128];
    __shared__ float s_sq[128];
    __shared__ int s_last;

    int tid = threadIdx.x;
    if (tid < 128) { s_sum[tid] = 0.f; s_sq[tid] = 0.f; }
    __syncthreads();

    int gwarp = blockIdx.x * (GAT_THREADS / 32) + (tid >> 5);
    int lane = tid & 31;

    float4 a4v = *(const float4*)(att + lane * 4);
    float4 b4 = *(const float4*)(bias + lane * 4);
    // pre-scaled attention: a6 = 0.6*att (for v-linear term), a4 = 0.4*att (for |v| term)
    float4 a6; a6.x = 0.6f * a4v.x; a6.y = 0.6f * a4v.y; a6.z = 0.6f * a4v.z; a6.w = 0.6f * a4v.w;
    float4 a4; a4.x = 0.4f * a4v.x; a4.y = 0.4f * a4v.y; a4.z = 0.4f * a4v.z; a4.w = 0.4f * a4v.w;

    float lsum[4] = {0.f, 0.f, 0.f, 0.f};
    float lsq[4]  = {0.f, 0.f, 0.f, 0.f};

    for (int node = gwarp; node < N; node += GAT_WARPS) {
        float4 xr4 = *(const float4*)(xr + (long long)node * D + lane * 4);
        // loop-invariant destination-side partial: sum(a6 * xr) over this lane's channels
        float axr6 = a6.x * xr4.x;
        axr6 = fmaf(a6.y, xr4.y, axr6);
        axr6 = fmaf(a6.z, xr4.z, axr6);
        axr6 = fmaf(a6.w, xr4.w, axr6);

        int beg = g_rowptr[node];
        int end = g_rowptr[node + 1];

        float s = 0.f;
        float4 acc = make_float4(0.f, 0.f, 0.f, 0.f);

        int e = beg;
        for (; e + 4 <= end; e += 4) {
            int si[4];
#pragma unroll
            for (int j = 0; j < 4; j++) si[j] = g_col[e + j];
            float4 ml[4];
#pragma unroll
            for (int j = 0; j < 4; j++) {
                uint2 raw = *(const uint2*)(xl + (long long)si[j] * D + lane * 4);
                float2 f01 = __half22float2(*(__half2*)&raw.x);
                float2 f23 = __half22float2(*(__half2*)&raw.y);
                ml[j] = make_float4(f01.x, f01.y, f23.x, f23.y);
            }
            float pt[4];
#pragma unroll
            for (int j = 0; j < 4; j++) {
                float t1 = axr6;                       // seeded with sum(a6*xr)
                t1 = fmaf(a6.x, ml[j].x, t1);
                t1 = fmaf(a6.y, ml[j].y, t1);
                t1 = fmaf(a6.z, ml[j].z, t1);
                t1 = fmaf(a6.w, ml[j].w, t1);
                float vx = ml[j].x + xr4.x;
                float vy = ml[j].y + xr4.y;
                float vz = ml[j].z + xr4.z;
                float vw = ml[j].w + xr4.w;
                float t2 = a4.x * fabsf(vx);           // |v| = free operand modifier
                t2 = fmaf(a4.y, fabsf(vy), t2);
                t2 = fmaf(a4.z, fabsf(vz), t2);
                t2 = fmaf(a4.w, fabsf(vw), t2);
                pt[j] = t1 + t2;
            }
#pragma unroll
            for (int j = 0; j < 4; j++) pt[j] += __shfl_xor_sync(0xffffffffu, pt[j], 1);
#pragma unroll
            for (int j = 0; j < 4; j++) pt[j] += __shfl_xor_sync(0xffffffffu, pt[j], 2);
#pragma unroll
            for (int j = 0; j < 4; j++) pt[j] += __shfl_xor_sync(0xffffffffu, pt[j], 4);
            float p[4];
#pragma unroll
            for (int j = 0; j < 4; j++) p[j] = __expf(fminf(pt[j], 80.f));
#pragma unroll
            for (int j = 0; j < 4; j++) {
                s += p[j];
                acc.x = fmaf(p[j], ml[j].x, acc.x);
                acc.y = fmaf(p[j], ml[j].y, acc.y);
                acc.z = fmaf(p[j], ml[j].z, acc.z);
                acc.w = fmaf(p[j], ml[j].w, acc.w);
            }
        }
        for (; e < end; e++) {
            int s0 = g_col[e];
            uint2 raw = *(const uint2*)(xl + (long long)s0 * D + lane * 4);
            float2 f01 = __half22float2(*(__half2*)&raw.x);
            float2 f23 = __half22float2(*(__half2*)&raw.y);
            float4 ml0 = make_float4(f01.x, f01.y, f23.x, f23.y);
            float t1 = axr6;
            t1 = fmaf(a6.x, ml0.x, t1);
            t1 = fmaf(a6.y, ml0.y, t1);
            t1 = fmaf(a6.z, ml0.z, t1);
            t1 = fmaf(a6.w, ml0.w, t1);
            float t2 = a4.x * fabsf(ml0.x + xr4.x);
            t2 = fmaf(a4.y, fabsf(ml0.y + xr4.y), t2);
            t2 = fmaf(a4.z, fabsf(ml0.z + xr4.z), t2);
            t2 = fmaf(a4.w, fabsf(ml0.w + xr4.w), t2);
            float pt = t1 + t2;
            pt += __shfl_xor_sync(0xffffffffu, pt, 1);
            pt += __shfl_xor_sync(0xffffffffu, pt, 2);
            pt += __shfl_xor_sync(0xffffffffu, pt, 4);
            float p = __expf(fminf(pt, 80.f));
            s += p;
            acc.x = fmaf(p, ml0.x, acc.x);
            acc.y = fmaf(p, ml0.y, acc.y);
            acc.z = fmaf(p, ml0.z, acc.z);
            acc.w = fmaf(p, ml0.w, acc.w);
        }

        float inv = 1.f / s;
        float4 r4 = *(const float4*)(xres + (long long)node * D + lane * 4);
        float4 o;
        o.x = acc.x * inv + b4.x + r4.x;
        o.y = acc.y * inv + b4.y + r4.y;
        o.z = acc.z * inv + b4.z + r4.z;
        o.w = acc.w * inv + b4.w + r4.w;
        *(float4*)(h + (long long)node * D + lane * 4) = o;

        lsum[0] += o.x; lsq[0] += o.x * o.x;
        lsum[1] += o.y; lsq[1] += o.y * o.y;
        lsum[2] += o.z; lsq[2] += o.z * o.z;
        lsum[3] += o.w; lsq[3] += o.w * o.w;
    }

    int c = lane * 4;
#pragma unroll
    for (int j = 0; j < 4; j++) {
        atomicAdd(&s_sum[c + j], lsum[j]);
        atomicAdd(&s_sq[c + j],  lsq[j]);
    }
    __syncthreads();

    if (tid < 128) {
        atomicAdd(&g_dsum[tid], (double)s_sum[tid]);
        atomicAdd(&g_dsq[tid],  (double)s_sq[tid]);
    }
    __threadfence();
    __syncthreads();
    if (tid == 0) {
        int t = atomicAdd(&g_ticket, 1);
        s_last = (t == (int)gridDim.x - 1) ? 1 : 0;
    }
    __syncthreads();

    if (s_last && tid < 128) {
        double mean = __ldcg(&g_dsum[tid]) / (double)N;
        double var  = __ldcg(&g_dsq[tid]) / (double)N - mean * mean;
        float inv = rsqrtf((float)var + BN_EPS);
        float sc = gamma[tid] * inv;
        g_scale[tid] = sc;
        g_shift[tid] = beta[tid] - (float)mean * sc;
    }
}

// ---------------- launch ----------------
extern "C" void kernel_launch(void* const* d_in, const int* in_sizes, int n_in,
                              void* d_out, int out_size) {
    const float* x     = (const float*)d_in[0];
    const void*  ei    = d_in[1];
    const float* Wl    = (const float*)d_in[2];
    const float* Wr    = (const float*)d_in[3];
    const float* att   = (const float*)d_in[4];
    const float* bias  = (const float*)d_in[5];
    const float* Wres  = (const float*)d_in[6];
    const float* gamma = (const float*)d_in[7];
    const float* beta  = (const float*)d_in[8];
    const float* Wout  = (const float*)d_in[9];
    const float* bout  = (const float*)d_in[10];
    int N = in_sizes[0] / D;
    int E = in_sizes[1] / 2;
    float* out = (float*)d_out;

    __half* p_xlh;
    float *p_xr, *p_xres, *p_h;
    cudaGetSymbolAddress((void**)&p_xlh, g_xl_h);
    cudaGetSymbolAddress((void**)&p_xr, g_xr);
    cudaGetSymbolAddress((void**)&p_xres, g_xres);
    cudaGetSymbolAddress((void**)&p_h, g_h);

    static cudaStream_t s2 = []() {
        cudaStream_t s; cudaStreamCreateWithFlags(&s, cudaStreamNonBlocking); return s;
    }();
    static cudaEvent_t ev_fork = []() {
        cudaEvent_t e; cudaEventCreateWithFlags(&e, cudaEventDisableTiming); return e;
    }();
    static cudaEvent_t ev_csr = []() {
        cudaEvent_t e; cudaEventCreateWithFlags(&e, cudaEventDisableTiming); return e;
    }();
    static bool attr_ok = []() {
        cudaFuncSetAttribute(k_gemm3, cudaFuncAttributeMaxDynamicSharedMemorySize,
                             GM_SMEM_BYTES);
        return true;
    }();
    (void)attr_ok;

    int Et = E + N;
    int nb = (N + 1023) / 1024;

    int mtiles = (N + GM_MT - 1) / GM_MT;
    dim3 g3(mtiles, 3);
    dim3 g1(mtiles, 1);

    // fork: CSR build on s2, overlapped with layer-0 GEMM on the main stream
    cudaEventRecord(ev_fork, 0);
    k_gemm3<<<g3, 512, GM_SMEM_BYTES>>>(x, Wl, Wr, Wres,
                                        p_xlh, p_xr, p_xres, nullptr, N, 0, 1);
    cudaStreamWaitEvent(s2, ev_fork, 0);
    k_count<<<(Et + 255) / 256, 256, 0, s2>>>(ei, E, N);
    k_scan1<<<nb, 1024, 0, s2>>>(N);
    k_scan3<<<nb, 1024, 0, s2>>>(N);
    k_scatter<<<(Et + 255) / 256, 256, 0, s2>>>(ei, E, N);
    cudaEventRecord(ev_csr, s2);
    cudaStreamWaitEvent(0, ev_csr, 0);  // join CSR before first edge pass

    const float* xin = x;
    for (int l = 0; l < 3; l++) {
        if (l > 0) {
            k_gemm3<<<g3, 512, GM_SMEM_BYTES>>>(xin,
                                                Wl + l * D * D, Wr + l * D * D,
                                                Wres + l * D * D,
                                                p_xlh, p_xr, p_xres, nullptr, N, 1, 1);
        }
        k_gat_bn<<<GAT_BLOCKS, GAT_THREADS>>>(p_xlh, p_xr, p_xres, att + l * D,
                                              bias + l * D, gamma + l * D,
                                              beta + l * D, p_h, N);
        xin = p_h;
    }
    k_gemm3<<<g1, 512, GM_SMEM_BYTES>>>(p_h, Wout, Wout, Wout,
                                        out, out, out, bout, N, 1, 0);
}

// round 11
// speedup vs baseline: 1.3833x; 1.2797x over previous
#include <cuda_runtime.h>
#include <cuda_fp16.h>
#include <math.h>

#define D 128
#define SLOPE 0.2f
#define BN_EPS 1e-5f
#define MAXN 50048
#define MAXET 901120

// GEMM tile config: 256-row M tile, full K=128 resident in smem
#define GM_MT 256
#define GM_AS_STRIDE 132
#define GM_SMEM_BYTES ((GM_MT * GM_AS_STRIDE + 128 * GM_AS_STRIDE) * 4)

// GAT kernel launch shape: pooled strided warp scheduling
#define GAT_BLOCKS 592
#define GAT_THREADS 256
#define GAT_WARPS (GAT_BLOCKS * (GAT_THREADS / 32))

// ---------------- scratch (static device globals: allocation-free) ----------------
__device__ __align__(16) __half g_xl_h[MAXN * D];   // fp16 source-transform (gathered)
__device__ __align__(16) __half g_xr_h[MAXN * D];   // fp16 target-transform (streamed)
__device__ __align__(16) float g_xres[MAXN * D];
__device__ __align__(16) float g_h[MAXN * D];
__device__ int g_deg[MAXN];
__device__ int g_cursor[MAXN];
__device__ int g_rowptr[MAXN + 1];
__device__ int g_col[MAXET];
__device__ int g_bsum[64];
__device__ double g_dsum[D];
__device__ double g_dsq[D];
__device__ __align__(16) float g_scale[D];
__device__ __align__(16) float g_shift[D];
__device__ int g_ticket;

// int64-vs-int32 probe: odd 32-bit words of the first 8 values all zero => int64.
__device__ __forceinline__ int probe_is64(const unsigned int* __restrict__ p) {
    unsigned int o = 0;
#pragma unroll
    for (int j = 1; j < 16; j += 2) o |= p[j];
    return o == 0u;
}

// ---------------- CSR build ----------------
__global__ void k_count(const void* __restrict__ ei, int E, int N) {
    __shared__ int s64;
    if (threadIdx.x == 0) s64 = probe_is64((const unsigned int*)ei);
    __syncthreads();
    int is64 = s64;
    int t = blockIdx.x * blockDim.x + threadIdx.x;
    int Et = E + N;
    if (t >= Et) return;
    int d;
    if (t < E) {
        d = is64 ? (int)((const long long*)ei)[(long long)E + t]
                 : ((const int*)ei)[E + t];
    } else {
        d = t - E;  // self loop
    }
    atomicAdd(&g_deg[d], 1);
}

__global__ void k_scan1(int N) {
    __shared__ int s[1024];
    int tid = threadIdx.x;
    int i = blockIdx.x * 1024 + tid;
    int v = (i < N) ? g_deg[i] : 0;
    if (i < N) { g_deg[i] = 0; g_cursor[i] = 0; }  // restore zeros for next call
    s[tid] = v;
    __syncthreads();
    for (int off = 1; off < 1024; off <<= 1) {
        int t = 0;
        if (tid >= off) t = s[tid - off];
        __syncthreads();
        if (tid >= off) s[tid] += t;
        __syncthreads();
    }
    if (i < N) g_rowptr[i + 1] = s[tid];
    if (tid == 1023) g_bsum[blockIdx.x] = s[1023];
}

__global__ void k_scan3(int N) {
    __shared__ int sbase;
    if (threadIdx.x == 0) {
        int acc = 0;
        for (int b = 0; b < blockIdx.x; b++) acc += g_bsum[b];
        sbase = acc;
    }
    __syncthreads();
    int i = blockIdx.x * 1024 + threadIdx.x;
    if (i < N) g_rowptr[i + 1] += sbase;
    if (i == 0) g_rowptr[0] = 0;
}

__global__ void k_scatter(const void* __restrict__ ei, int E, int N) {
    __shared__ int s64;
    if (threadIdx.x == 0) s64 = probe_is64((const unsigned int*)ei);
    __syncthreads();
    int is64 = s64;
    int t = blockIdx.x * blockDim.x + threadIdx.x;
    int Et = E + N;
    if (t >= Et) return;
    int s, d;
    if (t < E) {
        if (is64) {
            s = (int)((const long long*)ei)[t];
            d = (int)((const long long*)ei)[(long long)E + t];
        } else {
            s = ((const int*)ei)[t];
            d = ((const int*)ei)[E + t];
        }
    } else {
        s = d = t - E;
    }
    int pos = g_rowptr[d] + atomicAdd(&g_cursor[d], 1);
    g_col[pos] = s;
}

// ---------------- tf32 tensor-core GEMM (whole-K, single sync) ----------------
__device__ __forceinline__ unsigned f2tf(float x) {
    unsigned r;
    asm("cvt.rna.tf32.f32 %0, %1;" : "=r"(r) : "f"(x));
    return r;
}

__global__ void __launch_bounds__(512, 1)
k_gemm3(const float* __restrict__ A,
        const float* __restrict__ W0, const float* __restrict__ W1,
        const float* __restrict__ W2,
        void* __restrict__ C0v, void* __restrict__ C1v, float* __restrict__ C2,
        const float* __restrict__ bvec, int M, int affine, int c0half, int c1half) {
    const float* W = (blockIdx.y == 0) ? W0 : (blockIdx.y == 1 ? W1 : W2);
    void* Cv = (blockIdx.y == 0) ? C0v : (blockIdx.y == 1 ? C1v : (void*)C2);
    int ishalf = (blockIdx.y == 0) ? c0half : (blockIdx.y == 1 ? c1half : 0);

    extern __shared__ unsigned smem_u[];
    unsigned* As = smem_u;                            // [256][132]
    unsigned* Ws = smem_u + GM_MT * GM_AS_STRIDE;     // [128][132]

    int tid = threadIdx.x;
    int warp = tid >> 5;
    int lane = tid & 31;

    // zero BN accumulators for the following fused GAT+BN kernel
    if (blockIdx.x == 0 && blockIdx.y == 0) {
        if (tid < 128) { g_dsum[tid] = 0.0; g_dsq[tid] = 0.0; }
        if (tid == 0) g_ticket = 0;
    }

    int wm = warp >> 1;           // 0..7  -> 32-row slab
    int wn = warp & 1;            // 0..1  -> 64-col slab
    int m0 = blockIdx.x * GM_MT;

    int qr = lane >> 2;           // 0..7
    int qc = lane & 3;            // 0..3

    // ---- load full A tile (256 x 128) ----
#pragma unroll
    for (int it = 0; it < 16; it++) {
        int i = it * 512 + tid;
        int row = i >> 5;
        int col = (i & 31) * 4;
        int gm = m0 + row;
        float4 v = make_float4(0.f, 0.f, 0.f, 0.f);
        if (gm < M) v = *(const float4*)(A + (long long)gm * 128 + col);
        if (affine) {
            float4 sc = *(const float4*)(g_scale + col);
            float4 sh = *(const float4*)(g_shift + col);
            v.x = fmaf(v.x, sc.x, sh.x); v.x = v.x > 0.f ? v.x : v.x * SLOPE;
            v.y = fmaf(v.y, sc.y, sh.y); v.y = v.y > 0.f ? v.y : v.y * SLOPE;
            v.z = fmaf(v.z, sc.z, sh.z); v.z = v.z > 0.f ? v.z : v.z * SLOPE;
            v.w = fmaf(v.w, sc.w, sh.w); v.w = v.w > 0.f ? v.w : v.w * SLOPE;
        }
        unsigned* dst = As + row * GM_AS_STRIDE + col;
        dst[0] = f2tf(v.x); dst[1] = f2tf(v.y); dst[2] = f2tf(v.z); dst[3] = f2tf(v.w);
    }
    // ---- load full W (128 x 128) ----
#pragma unroll
    for (int it = 0; it < 8; it++) {
        int i = it * 512 + tid;
        int row = i >> 5;
        int col = (i & 31) * 4;
        float4 w = *(const float4*)(W + row * 128 + col);
        unsigned* dst = Ws + row * GM_AS_STRIDE + col;
        dst[0] = f2tf(w.x); dst[1] = f2tf(w.y); dst[2] = f2tf(w.z); dst[3] = f2tf(w.w);
    }
    __syncthreads();

    float acc[2][8][4];
#pragma unroll
    for (int i = 0; i < 2; i++)
#pragma unroll
        for (int j = 0; j < 8; j++)
#pragma unroll
            for (int k = 0; k < 4; k++) acc[i][j][k] = 0.f;

#pragma unroll
    for (int ks = 0; ks < 16; ks++) {
        int kb = ks * 8;
        unsigned a[2][4];
#pragma unroll
        for (int mi = 0; mi < 2; mi++) {
            int rb = wm * 32 + mi * 16 + qr;
            const unsigned* ap = As + rb * GM_AS_STRIDE + kb + qc;
            a[mi][0] = ap[0];
            a[mi][1] = ap[8 * GM_AS_STRIDE];
            a[mi][2] = ap[4];
            a[mi][3] = ap[8 * GM_AS_STRIDE + 4];
        }
#pragma unroll
        for (int ni = 0; ni < 8; ni++) {
            int n = wn * 64 + ni * 8 + qr;
            unsigned b0 = Ws[(kb + qc) * GM_AS_STRIDE + n];
            unsigned b1 = Ws[(kb + qc + 4) * GM_AS_STRIDE + n];
#pragma unroll
            for (int mi = 0; mi < 2; mi++) {
                asm volatile(
                    "mma.sync.aligned.m16n8k8.row.col.f32.tf32.tf32.f32 "
                    "{%0,%1,%2,%3}, {%4,%5,%6,%7}, {%8,%9}, {%0,%1,%2,%3};\n"
                    : "+f"(acc[mi][ni][0]), "+f"(acc[mi][ni][1]),
                      "+f"(acc[mi][ni][2]), "+f"(acc[mi][ni][3])
                    : "r"(a[mi][0]), "r"(a[mi][1]), "r"(a[mi][2]), "r"(a[mi][3]),
                      "r"(b0), "r"(b1));
            }
        }
    }

    // epilogue
    float* C = (float*)Cv;
    __half* Ch = (__half*)Cv;
#pragma unroll
    for (int mi = 0; mi < 2; mi++) {
        int r0 = m0 + wm * 32 + mi * 16 + qr;
#pragma unroll
        for (int ni = 0; ni < 8; ni++) {
            int col = wn * 64 + ni * 8 + qc * 2;
            float bx = 0.f, by = 0.f;
            if (bvec) { bx = bvec[col]; by = bvec[col + 1]; }
            if (ishalf) {
                if (r0 < M) {
                    __half2 o = __floats2half2_rn(acc[mi][ni][0] + bx, acc[mi][ni][1] + by);
                    *(__half2*)(Ch + (long long)r0 * 128 + col) = o;
                }
                if (r0 + 8 < M) {
                    __half2 o = __floats2half2_rn(acc[mi][ni][2] + bx, acc[mi][ni][3] + by);
                    *(__half2*)(Ch + (long long)(r0 + 8) * 128 + col) = o;
                }
            } else {
                if (r0 < M) {
                    float2 o; o.x = acc[mi][ni][0] + bx; o.y = acc[mi][ni][1] + by;
                    *(float2*)(C + (long long)r0 * 128 + col) = o;
                }
                if (r0 + 8 < M) {
                    float2 o; o.x = acc[mi][ni][2] + bx; o.y = acc[mi][ni][3] + by;
                    *(float2*)(C + (long long)(r0 + 8) * 128 + col) = o;
                }
            }
        }
    }
}

// ---------------- fused GATv2 edge pass + BN statistics + BN finalize ----------------
// xl AND xr in fp16 (gather 256B/warp/edge; xr streamed once per node).
// Softmax without running max (scores bounded; clamp at 80 for overflow safety).
// NOTE: this kernel sits exactly at the 64-reg/4-CTA occupancy cliff — do not
// add live registers (R8/R9 regressions both came from crossing it).
__device__ __forceinline__ float4 ld_h4(const __half* __restrict__ p,
                                        long long node, int lane) {
    uint2 raw = *(const uint2*)(p + node * D + lane * 4);
    float2 f01 = __half22float2(*(__half2*)&raw.x);
    float2 f23 = __half22float2(*(__half2*)&raw.y);
    return make_float4(f01.x, f01.y, f23.x, f23.y);
}

__device__ __forceinline__ float gat_score(float4 ml, float4 xr4, float4 a4) {
    float px = ml.x + xr4.x; px = px > 0.f ? px : px * SLOPE;
    float py = ml.y + xr4.y; py = py > 0.f ? py : py * SLOPE;
    float pz = ml.z + xr4.z; pz = pz > 0.f ? pz : pz * SLOPE;
    float pw = ml.w + xr4.w; pw = pw > 0.f ? pw : pw * SLOPE;
    return px * a4.x + py * a4.y + pz * a4.z + pw * a4.w;
}

__global__ void __launch_bounds__(GAT_THREADS)
k_gat_bn(const __half* __restrict__ xl, const __half* __restrict__ xr,
         const float* __restrict__ xres, const float* __restrict__ att,
         const float* __restrict__ bias,
         const float* __restrict__ gamma, const float* __restrict__ beta,
         float* __restrict__ h, int N) {
    __shared__ float s_sum[128];
    __shared__ float s_sq[128];
    __shared__ int s_last;

    int tid = threadIdx.x;
    if (tid < 128) { s_sum[tid] = 0.f; s_sq[tid] = 0.f; }
    __syncthreads();

    int gwarp = blockIdx.x * (GAT_THREADS / 32) + (tid >> 5);
    int lane = tid & 31;

    float4 a4 = *(const float4*)(att + lane * 4);
    float4 b4 = *(const float4*)(bias + lane * 4);

    float lsum[4] = {0.f, 0.f, 0.f, 0.f};
    float lsq[4]  = {0.f, 0.f, 0.f, 0.f};

    for (int node = gwarp; node < N; node += GAT_WARPS) {
        float4 xr4 = ld_h4(xr, node, lane);
        int beg = g_rowptr[node];
        int end = g_rowptr[node + 1];

        float s = 0.f;
        float4 acc = make_float4(0.f, 0.f, 0.f, 0.f);

        int e = beg;
        for (; e + 4 <= end; e += 4) {
            int si[4];
#pragma unroll
            for (int j = 0; j < 4; j++) si[j] = g_col[e + j];
            float4 ml[4];
#pragma unroll
            for (int j = 0; j < 4; j++) ml[j] = ld_h4(xl, si[j], lane);
            float pt[4];
#pragma unroll
            for (int j = 0; j < 4; j++) pt[j] = gat_score(ml[j], xr4, a4);
#pragma unroll
            for (int j = 0; j < 4; j++) pt[j] += __shfl_xor_sync(0xffffffffu, pt[j], 1);
#pragma unroll
            for (int j = 0; j < 4; j++) pt[j] += __shfl_xor_sync(0xffffffffu, pt[j], 2);
#pragma unroll
            for (int j = 0; j < 4; j++) pt[j] += __shfl_xor_sync(0xffffffffu, pt[j], 4);
            float p[4];
#pragma unroll
            for (int j = 0; j < 4; j++) p[j] = __expf(fminf(pt[j], 80.f));
#pragma unroll
            for (int j = 0; j < 4; j++) {
                s += p[j];
                acc.x = fmaf(p[j], ml[j].x, acc.x);
                acc.y = fmaf(p[j], ml[j].y, acc.y);
                acc.z = fmaf(p[j], ml[j].z, acc.z);
                acc.w = fmaf(p[j], ml[j].w, acc.w);
            }
        }
        for (; e < end; e++) {
            int s0 = g_col[e];
            float4 ml0 = ld_h4(xl, s0, lane);
            float pt = gat_score(ml0, xr4, a4);
            pt += __shfl_xor_sync(0xffffffffu, pt, 1);
            pt += __shfl_xor_sync(0xffffffffu, pt, 2);
            pt += __shfl_xor_sync(0xffffffffu, pt, 4);
            float p = __expf(fminf(pt, 80.f));
            s += p;
            acc.x = fmaf(p, ml0.x, acc.x);
            acc.y = fmaf(p, ml0.y, acc.y);
            acc.z = fmaf(p, ml0.z, acc.z);
            acc.w = fmaf(p, ml0.w, acc.w);
        }

        float inv = 1.f / s;
        float4 r4 = *(const float4*)(xres + (long long)node * D + lane * 4);
        float4 o;
        o.x = acc.x * inv + b4.x + r4.x;
        o.y = acc.y * inv + b4.y + r4.y;
        o.z = acc.z * inv + b4.z + r4.z;
        o.w = acc.w * inv + b4.w + r4.w;
        *(float4*)(h + (long long)node * D + lane * 4) = o;

        lsum[0] += o.x; lsq[0] += o.x * o.x;
        lsum[1] += o.y; lsq[1] += o.y * o.y;
        lsum[2] += o.z; lsq[2] += o.z * o.z;
        lsum[3] += o.w; lsq[3] += o.w * o.w;
    }

    int c = lane * 4;
#pragma unroll
    for (int j = 0; j < 4; j++) {
        atomicAdd(&s_sum[c + j], lsum[j]);
        atomicAdd(&s_sq[c + j],  lsq[j]);
    }
    __syncthreads();

    if (tid < 128) {
        atomicAdd(&g_dsum[tid], (double)s_sum[tid]);
        atomicAdd(&g_dsq[tid],  (double)s_sq[tid]);
    }
    __threadfence();
    __syncthreads();
    if (tid == 0) {
        int t = atomicAdd(&g_ticket, 1);
        s_last = (t == (int)gridDim.x - 1) ? 1 : 0;
    }
    __syncthreads();

    if (s_last && tid < 128) {
        double mean = __ldcg(&g_dsum[tid]) / (double)N;
        double var  = __ldcg(&g_dsq[tid]) / (double)N - mean * mean;
        float inv = rsqrtf((float)var + BN_EPS);
        float sc = gamma[tid] * inv;
        g_scale[tid] = sc;
        g_shift[tid] = beta[tid] - (float)mean * sc;
    }
}

// ---------------- launch ----------------
extern "C" void kernel_launch(void* const* d_in, const int* in_sizes, int n_in,
                              void* d_out, int out_size) {
    const float* x     = (const float*)d_in[0];
    const void*  ei    = d_in[1];
    const float* Wl    = (const float*)d_in[2];
    const float* Wr    = (const float*)d_in[3];
    const float* att   = (const float*)d_in[4];
    const float* bias  = (const float*)d_in[5];
    const float* Wres  = (const float*)d_in[6];
    const float* gamma = (const float*)d_in[7];
    const float* beta  = (const float*)d_in[8];
    const float* Wout  = (const float*)d_in[9];
    const float* bout  = (const float*)d_in[10];
    int N = in_sizes[0] / D;
    int E = in_sizes[1] / 2;
    float* out = (float*)d_out;

    __half *p_xlh, *p_xrh;
    float *p_xres, *p_h;
    cudaGetSymbolAddress((void**)&p_xlh, g_xl_h);
    cudaGetSymbolAddress((void**)&p_xrh, g_xr_h);
    cudaGetSymbolAddress((void**)&p_xres, g_xres);
    cudaGetSymbolAddress((void**)&p_h, g_h);

    static cudaStream_t s2 = []() {
        cudaStream_t s; cudaStreamCreateWithFlags(&s, cudaStreamNonBlocking); return s;
    }();
    static cudaEvent_t ev_fork = []() {
        cudaEvent_t e; cudaEventCreateWithFlags(&e, cudaEventDisableTiming); return e;
    }();
    static cudaEvent_t ev_csr = []() {
        cudaEvent_t e; cudaEventCreateWithFlags(&e, cudaEventDisableTiming); return e;
    }();
    static bool attr_ok = []() {
        cudaFuncSetAttribute(k_gemm3, cudaFuncAttributeMaxDynamicSharedMemorySize,
                             GM_SMEM_BYTES);
        return true;
    }();
    (void)attr_ok;

    int Et = E + N;
    int nb = (N + 1023) / 1024;

    int mtiles = (N + GM_MT - 1) / GM_MT;
    dim3 g3(mtiles, 3);
    dim3 g1(mtiles, 1);

    // fork: CSR build on s2, overlapped with layer-0 GEMM on the main stream
    cudaEventRecord(ev_fork, 0);
    k_gemm3<<<g3, 512, GM_SMEM_BYTES>>>(x, Wl, Wr, Wres,
                                        p_xlh, p_xrh, p_xres, nullptr, N, 0, 1, 1);
    cudaStreamWaitEvent(s2, ev_fork, 0);
    k_count<<<(Et + 255) / 256, 256, 0, s2>>>(ei, E, N);
    k_scan1<<<nb, 1024, 0, s2>>>(N);
    k_scan3<<<nb, 1024, 0, s2>>>(N);
    k_scatter<<<(Et + 255) / 256, 256, 0, s2>>>(ei, E, N);
    cudaEventRecord(ev_csr, s2);
    cudaStreamWaitEvent(0, ev_csr, 0);  // join CSR before first edge pass

    const float* xin = x;
    for (int l = 0; l < 3; l++) {
        if (l > 0) {
            k_gemm3<<<g3, 512, GM_SMEM_BYTES>>>(xin,
                                                Wl + l * D * D, Wr + l * D * D,
                                                Wres + l * D * D,
                                                p_xlh, p_xrh, p_xres, nullptr, N, 1, 1, 1);
        }
        k_gat_bn<<<GAT_BLOCKS, GAT_THREADS>>>(p_xlh, p_xrh, p_xres, att + l * D,
                                              bias + l * D, gamma + l * D,
                                              beta + l * D, p_h, N);
        xin = p_h;
    }
    k_gemm3<<<g1, 512, GM_SMEM_BYTES>>>(p_h, Wout, Wout, Wout,
                                        out, out, out, bout, N, 1, 0, 0);
}

// round 12
// speedup vs baseline: 1.4575x; 1.0536x over previous
#include <cuda_runtime.h>
#include <cuda_fp16.h>
#include <math.h>

#define D 128
#define SLOPE 0.2f
#define BN_EPS 1e-5f
#define MAXN 50048
#define MAXET 901120

// GEMM tile config: 256-row M tile, full K=128 resident in smem (fp16)
#define GM_MT 256
#define GM_HS 136   // half-element stride: bank = 4*qr + qc = lane (conflict-free)
#define GM_SMEM_BYTES ((GM_MT * GM_HS + 128 * GM_HS) * 2)

// GAT kernel launch shape: pooled strided warp scheduling
#define GAT_BLOCKS 592
#define GAT_THREADS 256
#define GAT_WARPS (GAT_BLOCKS * (GAT_THREADS / 32))

// ---------------- scratch (static device globals: allocation-free) ----------------
__device__ __align__(16) __half g_xl_h[MAXN * D];   // fp16 source-transform (gathered)
__device__ __align__(16) float g_xr[MAXN * D];
__device__ __align__(16) float g_xres[MAXN * D];
__device__ __align__(16) float g_h[MAXN * D];
__device__ int g_deg[MAXN];
__device__ int g_cursor[MAXN];
__device__ int g_rowptr[MAXN + 1];
__device__ int g_col[MAXET];
__device__ int g_bsum[64];
__device__ double g_dsum[D];
__device__ double g_dsq[D];
__device__ __align__(16) float g_scale[D];
__device__ __align__(16) float g_shift[D];
__device__ int g_ticket;

// int64-vs-int32 probe: odd 32-bit words of the first 8 values all zero => int64.
__device__ __forceinline__ int probe_is64(const unsigned int* __restrict__ p) {
    unsigned int o = 0;
#pragma unroll
    for (int j = 1; j < 16; j += 2) o |= p[j];
    return o == 0u;
}

// ---------------- CSR build ----------------
__global__ void k_count(const void* __restrict__ ei, int E, int N) {
    __shared__ int s64;
    if (threadIdx.x == 0) s64 = probe_is64((const unsigned int*)ei);
    __syncthreads();
    int is64 = s64;
    int t = blockIdx.x * blockDim.x + threadIdx.x;
    int Et = E + N;
    if (t >= Et) return;
    int d;
    if (t < E) {
        d = is64 ? (int)((const long long*)ei)[(long long)E + t]
                 : ((const int*)ei)[E + t];
    } else {
        d = t - E;  // self loop
    }
    atomicAdd(&g_deg[d], 1);
}

__global__ void k_scan1(int N) {
    __shared__ int s[1024];
    int tid = threadIdx.x;
    int i = blockIdx.x * 1024 + tid;
    int v = (i < N) ? g_deg[i] : 0;
    if (i < N) { g_deg[i] = 0; g_cursor[i] = 0; }  // restore zeros for next call
    s[tid] = v;
    __syncthreads();
    for (int off = 1; off < 1024; off <<= 1) {
        int t = 0;
        if (tid >= off) t = s[tid - off];
        __syncthreads();
        if (tid >= off) s[tid] += t;
        __syncthreads();
    }
    if (i < N) g_rowptr[i + 1] = s[tid];
    if (tid == 1023) g_bsum[blockIdx.x] = s[1023];
}

__global__ void k_scan3(int N) {
    __shared__ int sbase;
    if (threadIdx.x == 0) {
        int acc = 0;
        for (int b = 0; b < blockIdx.x; b++) acc += g_bsum[b];
        sbase = acc;
    }
    __syncthreads();
    int i = blockIdx.x * 1024 + threadIdx.x;
    if (i < N) g_rowptr[i + 1] += sbase;
    if (i == 0) g_rowptr[0] = 0;
}

__global__ void k_scatter(const void* __restrict__ ei, int E, int N) {
    __shared__ int s64;
    if (threadIdx.x == 0) s64 = probe_is64((const unsigned int*)ei);
    __syncthreads();
    int is64 = s64;
    int t = blockIdx.x * blockDim.x + threadIdx.x;
    int Et = E + N;
    if (t >= Et) return;
    int s, d;
    if (t < E) {
        if (is64) {
            s = (int)((const long long*)ei)[t];
            d = (int)((const long long*)ei)[(long long)E + t];
        } else {
            s = ((const int*)ei)[t];
            d = ((const int*)ei)[E + t];
        }
    } else {
        s = d = t - E;
    }
    int pos = g_rowptr[d] + atomicAdd(&g_cursor[d], 1);
    g_col[pos] = s;
}

// ---------------- fp16 tensor-core GEMM (m16n8k16, whole-K, single sync) ----------------
// C[M,128] = act(A)[M,128] @ W[128,128] (+bias)
// fp16 inputs have the SAME 11-bit effective mantissa as tf32; fp32 accumulate.
// 2x tensor rate + half the MMA/LDS instructions vs tf32 k8.
// Block: 512 threads (16 warps, 8x2), C tile 256x128, warp tile 32x64.
__global__ void __launch_bounds__(512, 1)
k_gemm3(const float* __restrict__ A,
        const float* __restrict__ W0, const float* __restrict__ W1,
        const float* __restrict__ W2,
        void* __restrict__ C0v, void* __restrict__ C1v, float* __restrict__ C2,
        const float* __restrict__ bvec, int M, int affine, int c0half, int c1half) {
    const float* W = (blockIdx.y == 0) ? W0 : (blockIdx.y == 1 ? W1 : W2);
    void* Cv = (blockIdx.y == 0) ? C0v : (blockIdx.y == 1 ? C1v : (void*)C2);
    int ishalf = (blockIdx.y == 0) ? c0half : (blockIdx.y == 1 ? c1half : 0);

    extern __shared__ __half smem_h[];
    __half* As = smem_h;                    // [256][GM_HS]  (row-major, k contig)
    __half* Ws = smem_h + GM_MT * GM_HS;    // [128][GM_HS]  (TRANSPOSED: [n][k])

    int tid = threadIdx.x;
    int warp = tid >> 5;
    int lane = tid & 31;

    // zero BN accumulators for the following fused GAT+BN kernel
    if (blockIdx.x == 0 && blockIdx.y == 0) {
        if (tid < 128) { g_dsum[tid] = 0.0; g_dsq[tid] = 0.0; }
        if (tid == 0) g_ticket = 0;
    }

    int wm = warp >> 1;           // 0..7  -> 32-row slab
    int wn = warp & 1;            // 0..1  -> 64-col slab
    int m0 = blockIdx.x * GM_MT;

    int qr = lane >> 2;           // 0..7
    int qc = lane & 3;            // 0..3

    // ---- load full A tile (256 x 128) -> fp16 ----
#pragma unroll
    for (int it = 0; it < 16; it++) {
        int i = it * 512 + tid;
        int row = i >> 5;
        int col = (i & 31) * 4;
        int gm = m0 + row;
        float4 v = make_float4(0.f, 0.f, 0.f, 0.f);
        if (gm < M) v = *(const float4*)(A + (long long)gm * 128 + col);
        if (affine) {
            float4 sc = *(const float4*)(g_scale + col);
            float4 sh = *(const float4*)(g_shift + col);
            v.x = fmaf(v.x, sc.x, sh.x); v.x = v.x > 0.f ? v.x : v.x * SLOPE;
            v.y = fmaf(v.y, sc.y, sh.y); v.y = v.y > 0.f ? v.y : v.y * SLOPE;
            v.z = fmaf(v.z, sc.z, sh.z); v.z = v.z > 0.f ? v.z : v.z * SLOPE;
            v.w = fmaf(v.w, sc.w, sh.w); v.w = v.w > 0.f ? v.w : v.w * SLOPE;
        }
        __half* dst = As + row * GM_HS + col;
        *(__half2*)(dst)     = __floats2half2_rn(v.x, v.y);
        *(__half2*)(dst + 2) = __floats2half2_rn(v.z, v.w);
    }
    // ---- load full W (128 x 128) TRANSPOSED -> Ws[n][k] fp16 ----
#pragma unroll
    for (int it = 0; it < 8; it++) {
        int i = it * 512 + tid;
        int row = i >> 5;              // k index 0..127
        int col = (i & 31) * 4;        // n base
        float4 w = *(const float4*)(W + row * 128 + col);
        Ws[(col + 0) * GM_HS + row] = __float2half_rn(w.x);
        Ws[(col + 1) * GM_HS + row] = __float2half_rn(w.y);
        Ws[(col + 2) * GM_HS + row] = __float2half_rn(w.z);
        Ws[(col + 3) * GM_HS + row] = __float2half_rn(w.w);
    }
    __syncthreads();

    float acc[2][8][4];
#pragma unroll
    for (int i = 0; i < 2; i++)
#pragma unroll
        for (int j = 0; j < 8; j++)
#pragma unroll
            for (int k = 0; k < 4; k++) acc[i][j][k] = 0.f;

#pragma unroll
    for (int ks = 0; ks < 8; ks++) {
        int kb = ks * 16;
        unsigned a[2][4];
#pragma unroll
        for (int mi = 0; mi < 2; mi++) {
            int rb = wm * 32 + mi * 16 + qr;
            const __half* ap = As + rb * GM_HS + kb + 2 * qc;
            a[mi][0] = *(const unsigned*)(ap);                  // rows qr,   k 2qc..
            a[mi][1] = *(const unsigned*)(ap + 8 * GM_HS);      // rows qr+8
            a[mi][2] = *(const unsigned*)(ap + 8);              // k+8
            a[mi][3] = *(const unsigned*)(ap + 8 * GM_HS + 8);
        }
#pragma unroll
        for (int ni = 0; ni < 8; ni++) {
            int n = wn * 64 + ni * 8 + qr;
            const __half* bp = Ws + n * GM_HS + kb + 2 * qc;
            unsigned b0 = *(const unsigned*)(bp);               // k 2qc,2qc+1 @ col n
            unsigned b1 = *(const unsigned*)(bp + 8);           // k+8
#pragma unroll
            for (int mi = 0; mi < 2; mi++) {
                asm volatile(
                    "mma.sync.aligned.m16n8k16.row.col.f32.f16.f16.f32 "
                    "{%0,%1,%2,%3}, {%4,%5,%6,%7}, {%8,%9}, {%0,%1,%2,%3};\n"
                    : "+f"(acc[mi][ni][0]), "+f"(acc[mi][ni][1]),
                      "+f"(acc[mi][ni][2]), "+f"(acc[mi][ni][3])
                    : "r"(a[mi][0]), "r"(a[mi][1]), "r"(a[mi][2]), "r"(a[mi][3]),
                      "r"(b0), "r"(b1));
            }
        }
    }

    // epilogue (accumulator layout identical to the tf32 version)
    float* C = (float*)Cv;
    __half* Ch = (__half*)Cv;
#pragma unroll
    for (int mi = 0; mi < 2; mi++) {
        int r0 = m0 + wm * 32 + mi * 16 + qr;
#pragma unroll
        for (int ni = 0; ni < 8; ni++) {
            int col = wn * 64 + ni * 8 + qc * 2;
            float bx = 0.f, by = 0.f;
            if (bvec) { bx = bvec[col]; by = bvec[col + 1]; }
            if (ishalf) {
                if (r0 < M) {
                    __half2 o = __floats2half2_rn(acc[mi][ni][0] + bx, acc[mi][ni][1] + by);
                    *(__half2*)(Ch + (long long)r0 * 128 + col) = o;
                }
                if (r0 + 8 < M) {
                    __half2 o = __floats2half2_rn(acc[mi][ni][2] + bx, acc[mi][ni][3] + by);
                    *(__half2*)(Ch + (long long)(r0 + 8) * 128 + col) = o;
                }
            } else {
                if (r0 < M) {
                    float2 o; o.x = acc[mi][ni][0] + bx; o.y = acc[mi][ni][1] + by;
                    *(float2*)(C + (long long)r0 * 128 + col) = o;
                }
                if (r0 + 8 < M) {
                    float2 o; o.x = acc[mi][ni][2] + bx; o.y = acc[mi][ni][3] + by;
                    *(float2*)(C + (long long)(r0 + 8) * 128 + col) = o;
                }
            }
        }
    }
}

// ---------------- fused GATv2 edge pass + BN statistics + BN finalize ----------------
// R8 measured-best configuration: xl fp16 (gathered), xr/xres fp32 (streamed).
// Softmax without running max (scores bounded; clamp at 80 for overflow safety).
// NOTE: occupancy-critical at the 64-reg/4-CTA cliff — do not add live registers.
__device__ __forceinline__ float4 ld_h4(const __half* __restrict__ p,
                                        long long node, int lane) {
    uint2 raw = *(const uint2*)(p + node * D + lane * 4);
    float2 f01 = __half22float2(*(__half2*)&raw.x);
    float2 f23 = __half22float2(*(__half2*)&raw.y);
    return make_float4(f01.x, f01.y, f23.x, f23.y);
}

__device__ __forceinline__ float gat_score(float4 ml, float4 xr4, float4 a4) {
    float px = ml.x + xr4.x; px = px > 0.f ? px : px * SLOPE;
    float py = ml.y + xr4.y; py = py > 0.f ? py : py * SLOPE;
    float pz = ml.z + xr4.z; pz = pz > 0.f ? pz : pz * SLOPE;
    float pw = ml.w + xr4.w; pw = pw > 0.f ? pw : pw * SLOPE;
    return px * a4.x + py * a4.y + pz * a4.z + pw * a4.w;
}

__global__ void __launch_bounds__(GAT_THREADS)
k_gat_bn(const __half* __restrict__ xl, const float* __restrict__ xr,
         const float* __restrict__ xres, const float* __restrict__ att,
         const float* __restrict__ bias,
         const float* __restrict__ gamma, const float* __restrict__ beta,
         float* __restrict__ h, int N) {
    __shared__ float s_sum[128];
    __shared__ float s_sq[128];
    __shared__ int s_last;

    int tid = threadIdx.x;
    if (tid < 128) { s_sum[tid] = 0.f; s_sq[tid] = 0.f; }
    __syncthreads();

    int gwarp = blockIdx.x * (GAT_THREADS / 32) + (tid >> 5);
    int lane = tid & 31;

    float4 a4 = *(const float4*)(att + lane * 4);
    float4 b4 = *(const float4*)(bias + lane * 4);

    float lsum[4] = {0.f, 0.f, 0.f, 0.f};
    float lsq[4]  = {0.f, 0.f, 0.f, 0.f};

    for (int node = gwarp; node < N; node += GAT_WARPS) {
        float4 xr4 = *(const float4*)(xr + (long long)node * D + lane * 4);
        int beg = g_rowptr[node];
        int end = g_rowptr[node + 1];

        float s = 0.f;
        float4 acc = make_float4(0.f, 0.f, 0.f, 0.f);

        int e = beg;
        for (; e + 4 <= end; e += 4) {
            int si[4];
#pragma unroll
            for (int j = 0; j < 4; j++) si[j] = g_col[e + j];
            float4 ml[4];
#pragma unroll
            for (int j = 0; j < 4; j++) ml[j] = ld_h4(xl, si[j], lane);
            float pt[4];
#pragma unroll
            for (int j = 0; j < 4; j++) pt[j] = gat_score(ml[j], xr4, a4);
#pragma unroll
            for (int j = 0; j < 4; j++) pt[j] += __shfl_xor_sync(0xffffffffu, pt[j], 1);
#pragma unroll
            for (int j = 0; j < 4; j++) pt[j] += __shfl_xor_sync(0xffffffffu, pt[j], 2);
#pragma unroll
            for (int j = 0; j < 4; j++) pt[j] += __shfl_xor_sync(0xffffffffu, pt[j], 4);
            float p[4];
#pragma unroll
            for (int j = 0; j < 4; j++) p[j] = __expf(fminf(pt[j], 80.f));
#pragma unroll
            for (int j = 0; j < 4; j++) {
                s += p[j];
                acc.x = fmaf(p[j], ml[j].x, acc.x);
                acc.y = fmaf(p[j], ml[j].y, acc.y);
                acc.z = fmaf(p[j], ml[j].z, acc.z);
                acc.w = fmaf(p[j], ml[j].w, acc.w);
            }
        }
        for (; e < end; e++) {
            int s0 = g_col[e];
            float4 ml0 = ld_h4(xl, s0, lane);
            float pt = gat_score(ml0, xr4, a4);
            pt += __shfl_xor_sync(0xffffffffu, pt, 1);
            pt += __shfl_xor_sync(0xffffffffu, pt, 2);
            pt += __shfl_xor_sync(0xffffffffu, pt, 4);
            float p = __expf(fminf(pt, 80.f));
            s += p;
            acc.x = fmaf(p, ml0.x, acc.x);
            acc.y = fmaf(p, ml0.y, acc.y);
            acc.z = fmaf(p, ml0.z, acc.z);
            acc.w = fmaf(p, ml0.w, acc.w);
        }

        float inv = 1.f / s;
        float4 r4 = *(const float4*)(xres + (long long)node * D + lane * 4);
        float4 o;
        o.x = acc.x * inv + b4.x + r4.x;
        o.y = acc.y * inv + b4.y + r4.y;
        o.z = acc.z * inv + b4.z + r4.z;
        o.w = acc.w * inv + b4.w + r4.w;
        *(float4*)(h + (long long)node * D + lane * 4) = o;

        lsum[0] += o.x; lsq[0] += o.x * o.x;
        lsum[1] += o.y; lsq[1] += o.y * o.y;
        lsum[2] += o.z; lsq[2] += o.z * o.z;
        lsum[3] += o.w; lsq[3] += o.w * o.w;
    }

    int c = lane * 4;
#pragma unroll
    for (int j = 0; j < 4; j++) {
        atomicAdd(&s_sum[c + j], lsum[j]);
        atomicAdd(&s_sq[c + j],  lsq[j]);
    }
    __syncthreads();

    if (tid < 128) {
        atomicAdd(&g_dsum[tid], (double)s_sum[tid]);
        atomicAdd(&g_dsq[tid],  (double)s_sq[tid]);
    }
    __threadfence();
    __syncthreads();
    if (tid == 0) {
        int t = atomicAdd(&g_ticket, 1);
        s_last = (t == (int)gridDim.x - 1) ? 1 : 0;
    }
    __syncthreads();

    if (s_last && tid < 128) {
        double mean = __ldcg(&g_dsum[tid]) / (double)N;
        double var  = __ldcg(&g_dsq[tid]) / (double)N - mean * mean;
        float inv = rsqrtf((float)var + BN_EPS);
        float sc = gamma[tid] * inv;
        g_scale[tid] = sc;
        g_shift[tid] = beta[tid] - (float)mean * sc;
    }
}

// ---------------- launch ----------------
extern "C" void kernel_launch(void* const* d_in, const int* in_sizes, int n_in,
                              void* d_out, int out_size) {
    const float* x     = (const float*)d_in[0];
    const void*  ei    = d_in[1];
    const float* Wl    = (const float*)d_in[2];
    const float* Wr    = (const float*)d_in[3];
    const float* att   = (const float*)d_in[4];
    const float* bias  = (const float*)d_in[5];
    const float* Wres  = (const float*)d_in[6];
    const float* gamma = (const float*)d_in[7];
    const float* beta  = (const float*)d_in[8];
    const float* Wout  = (const float*)d_in[9];
    const float* bout  = (const float*)d_in[10];
    int N = in_sizes[0] / D;
    int E = in_sizes[1] / 2;
    float* out = (float*)d_out;

    __half* p_xlh;
    float *p_xr, *p_xres, *p_h;
    cudaGetSymbolAddress((void**)&p_xlh, g_xl_h);
    cudaGetSymbolAddress((void**)&p_xr, g_xr);
    cudaGetSymbolAddress((void**)&p_xres, g_xres);
    cudaGetSymbolAddress((void**)&p_h, g_h);

    static cudaStream_t s2 = []() {
        cudaStream_t s; cudaStreamCreateWithFlags(&s, cudaStreamNonBlocking); return s;
    }();
    static cudaEvent_t ev_fork = []() {
        cudaEvent_t e; cudaEventCreateWithFlags(&e, cudaEventDisableTiming); return e;
    }();
    static cudaEvent_t ev_csr = []() {
        cudaEvent_t e; cudaEventCreateWithFlags(&e, cudaEventDisableTiming); return e;
    }();
    static bool attr_ok = []() {
        cudaFuncSetAttribute(k_gemm3, cudaFuncAttributeMaxDynamicSharedMemorySize,
                             GM_SMEM_BYTES);
        return true;
    }();
    (void)attr_ok;

    int Et = E + N;
    int nb = (N + 1023) / 1024;

    int mtiles = (N + GM_MT - 1) / GM_MT;
    dim3 g3(mtiles, 3);
    dim3 g1(mtiles, 1);

    // fork: CSR build on s2, overlapped with layer-0 GEMM on the main stream
    cudaEventRecord(ev_fork, 0);
    k_gemm3<<<g3, 512, GM_SMEM_BYTES>>>(x, Wl, Wr, Wres,
                                        p_xlh, p_xr, p_xres, nullptr, N, 0, 1, 0);
    cudaStreamWaitEvent(s2, ev_fork, 0);
    k_count<<<(Et + 255) / 256, 256, 0, s2>>>(ei, E, N);
    k_scan1<<<nb, 1024, 0, s2>>>(N);
    k_scan3<<<nb, 1024, 0, s2>>>(N);
    k_scatter<<<(Et + 255) / 256, 256, 0, s2>>>(ei, E, N);
    cudaEventRecord(ev_csr, s2);
    cudaStreamWaitEvent(0, ev_csr, 0);  // join CSR before first edge pass

    const float* xin = x;
    for (int l = 0; l < 3; l++) {
        if (l > 0) {
            k_gemm3<<<g3, 512, GM_SMEM_BYTES>>>(xin,
                                                Wl + l * D * D, Wr + l * D * D,
                                                Wres + l * D * D,
                                                p_xlh, p_xr, p_xres, nullptr, N, 1, 1, 0);
        }
        k_gat_bn<<<GAT_BLOCKS, GAT_THREADS>>>(p_xlh, p_xr, p_xres, att + l * D,
                                              bias + l * D, gamma + l * D,
                                              beta + l * D, p_h, N);
        xin = p_h;
    }
    k_gemm3<<<g1, 512, GM_SMEM_BYTES>>>(p_h, Wout, Wout, Wout,
                                        out, out, out, bout, N, 1, 0, 0);
}